// round 4
// baseline (speedup 1.0000x reference)
#include <cuda_runtime.h>
#include <cuda_fp16.h>

#define CANVAS 1024
#define NSH 64
#define TEXN 512
#define QDIM 513                 // tap-origin range (+1 offset): 0..512
#define QPAIR 257                // ceil(QDIM/2), 2x2 morton blocks per axis
#define QT (QPAIR * QPAIR * 4)   // entries per texture (swizzled, padded)
#define T_EPS 1e-5f

// One quad entry = the 2x2 bilinear tap block for tap-origin (yi, xi):
//   a: v00.rg, v00.ba, v01.rg, v01.ba   (fp16 pairs)
//   b: v10.rg, v10.ba, v11.rg, v11.ba
// Out-of-bounds taps stored as zero (matches reference zero-fill).
// Layout: 2x2 Morton blocks -> one 128B line = 2x2 neighborhood of tap origins.
struct __align__(32) Quad { uint4 a, b; };

__device__ Quad g_quad[4 * QT];   // ~33.8 MB scratch

__device__ __forceinline__ int quad_off(int qy, int qx) {
    return ((((qy >> 1) * QPAIR + (qx >> 1)) << 2) | ((qy & 1) << 1) | (qx & 1));
}

// Per-shape transform/color record (smem), bbox kept separate for cheap cull.
struct __align__(16) ShapeXfm {
    float tx, ty, m00, m01;
    float m10, m11, r, g;
    float b; int texoff; float pad0, pad1;
};

// ---------------------------------------------------------------------------
// Kernel 1: build fp16 quad-gather table (Morton-swizzled).
// grid: (QDIM rows, 4 tex), block 256.
// ---------------------------------------------------------------------------
__global__ __launch_bounds__(256) void build_quad_kernel(const float* __restrict__ tex) {
    int t  = blockIdx.y;
    int qy = blockIdx.x;                   // 0..512
    int yi = qy - 1;                       // -1..511
    const int NPIX = TEXN * TEXN;
    const float* base = tex + (size_t)t * 4 * NPIX;
    Quad* qbase = g_quad + t * QT;

    for (int qx = threadIdx.x; qx < QDIM; qx += 256) {
        int xi = qx - 1;                   // -1..511

        float vals[4][4];  // [tap][chan]
        #pragma unroll
        for (int ty2 = 0; ty2 < 2; ty2++) {
            #pragma unroll
            for (int tx2 = 0; tx2 < 2; tx2++) {
                int y = yi + ty2, x = xi + tx2;
                bool ok = ((unsigned)x < (unsigned)TEXN) && ((unsigned)y < (unsigned)TEXN);
                int off = y * TEXN + x;
                #pragma unroll
                for (int ch = 0; ch < 4; ch++)
                    vals[ty2 * 2 + tx2][ch] = ok ? __ldg(base + ch * NPIX + off) : 0.0f;
            }
        }

        __half2 h[8];
        #pragma unroll
        for (int tap = 0; tap < 4; tap++) {
            h[tap * 2 + 0] = __floats2half2_rn(vals[tap][0], vals[tap][1]);
            h[tap * 2 + 1] = __floats2half2_rn(vals[tap][2], vals[tap][3]);
        }

        Quad q;
        q.a = *reinterpret_cast<uint4*>(&h[0]);
        q.b = *reinterpret_cast<uint4*>(&h[4]);
        qbase[quad_off(qy, qx)] = q;
    }
}

// ---------------------------------------------------------------------------
// Kernel 2: render. One thread per pixel. Reverse-order compositing with
// transmittance early-exit. Shape prep fused into smem fill.
// ---------------------------------------------------------------------------
__global__ __launch_bounds__(256) void render_kernel(const int* __restrict__ st,
                                                     const float* __restrict__ params,
                                                     float* __restrict__ out) {
    __shared__ float4   sbox[NSH];   // bx0, bx1, by0, by1
    __shared__ ShapeXfm sxf[NSH];

    int tid = threadIdx.y * 32 + threadIdx.x;
    if (tid < NSH) {
        const float* p = params + tid * 9;
        float tx = p[0] * (float)CANVAS;
        float ty = p[1] * (float)CANVAS;
        float W  = (float)CANVAS * (0.05f + 0.95f * p[2]);
        float H  = (float)CANVAS * (0.05f + 0.95f * p[3]);
        float as = p[4], ac = p[5];
        float nrm = sqrtf(as * as + ac * ac) + 1e-8f;
        float c = ac / nrm, s = as / nrm;
        float fx = (float)TEXN / W;
        float fy = (float)TEXN / H;

        ShapeXfm xf;
        xf.tx = tx; xf.ty = ty;
        xf.m00 =  c * fx;  xf.m01 = s * fx;
        xf.m10 = -s * fy;  xf.m11 = c * fy;
        xf.r = p[6]; xf.g = p[7]; xf.b = p[8];
        xf.texoff = st[tid] * QT;
        xf.pad0 = xf.pad1 = 0.f;
        sxf[tid] = xf;

        float uh = 0.5f * W * (1.0f + 2.0f / TEXN) + 2.0f;
        float vh = 0.5f * H * (1.0f + 2.0f / TEXN) + 2.0f;
        float ex = fabsf(c) * uh + fabsf(s) * vh;
        float ey = fabsf(s) * uh + fabsf(c) * vh;
        sbox[tid] = make_float4(tx - ex, tx + ex, ty - ey, ty + ey);
    }
    __syncthreads();

    int x = blockIdx.x * 32 + threadIdx.x;
    int y = blockIdx.y * 8 + threadIdx.y;
    float px = (float)x + 0.5f;
    float py = (float)y + 0.5f;

    float tX0 = (float)(blockIdx.x * 32) + 0.5f;
    float tX1 = tX0 + 31.0f;
    float tY0 = (float)(blockIdx.y * 8) + 0.5f;
    float tY1 = tY0 + 7.0f;

    // Reverse compositing: out = C + T * canvas0(=1)
    float Cr = 0.0f, Cg = 0.0f, Cb = 0.0f;
    float T = 1.0f;

    for (int si = NSH - 1; si >= 0; si--) {
        // warp-uniform break: every lane saturated
        if (__all_sync(0xffffffffu, T <= T_EPS)) break;

        float4 bb = sbox[si];
        // block-uniform bbox cull
        if (tX1 < bb.x || tX0 > bb.y || tY1 < bb.z || tY0 > bb.w)
            continue;
        if (T <= T_EPS) continue;   // per-lane: no more visible contribution

        const ShapeXfm rec = sxf[si];
        float dx = px - rec.tx;
        float dy = py - rec.ty;
        float u = fmaf(rec.m00, dx, fmaf(rec.m01, dy, 255.5f));
        float v = fmaf(rec.m10, dx, fmaf(rec.m11, dy, 255.5f));
        if (!(u > -1.0f && u < (float)TEXN && v > -1.0f && v < (float)TEXN))
            continue;

        float xf = floorf(u), yf = floorf(v);
        float wx = u - xf,    wy = v - yf;
        int xi = (int)xf, yi = (int)yf;   // -1..511

        const uint4* q = reinterpret_cast<const uint4*>(
            g_quad + rec.texoff + quad_off(yi + 1, xi + 1));
        uint4 qa = __ldg(q);
        uint4 qb = __ldg(q + 1);

        float w00 = (1.0f - wx) * (1.0f - wy);
        float w01 = wx * (1.0f - wy);
        float w10 = (1.0f - wx) * wy;
        float w11 = wx * wy;

        float2 rg00 = __half22float2(*reinterpret_cast<const __half2*>(&qa.x));
        float2 ba00 = __half22float2(*reinterpret_cast<const __half2*>(&qa.y));
        float2 rg01 = __half22float2(*reinterpret_cast<const __half2*>(&qa.z));
        float2 ba01 = __half22float2(*reinterpret_cast<const __half2*>(&qa.w));
        float2 rg10 = __half22float2(*reinterpret_cast<const __half2*>(&qb.x));
        float2 ba10 = __half22float2(*reinterpret_cast<const __half2*>(&qb.y));
        float2 rg11 = __half22float2(*reinterpret_cast<const __half2*>(&qb.z));
        float2 ba11 = __half22float2(*reinterpret_cast<const __half2*>(&qb.w));

        float sr = fmaf(rg00.x, w00, fmaf(rg01.x, w01, fmaf(rg10.x, w10, rg11.x * w11)));
        float sg = fmaf(rg00.y, w00, fmaf(rg01.y, w01, fmaf(rg10.y, w10, rg11.y * w11)));
        float sb = fmaf(ba00.x, w00, fmaf(ba01.x, w01, fmaf(ba10.x, w10, ba11.x * w11)));
        float sa = fmaf(ba00.y, w00, fmaf(ba01.y, w01, fmaf(ba10.y, w10, ba11.y * w11)));

        float Ta = T * sa;
        Cr = fmaf(Ta, sr * rec.r, Cr);
        Cg = fmaf(Ta, sg * rec.g, Cg);
        Cb = fmaf(Ta, sb * rec.b, Cb);
        T  = T - Ta;            // T *= (1 - sa)
    }

    int o = y * CANVAS + x;
    out[o] = Cr + T;
    out[CANVAS * CANVAS + o] = Cg + T;
    out[2 * CANVAS * CANVAS + o] = Cb + T;
}

// ---------------------------------------------------------------------------
extern "C" void kernel_launch(void* const* d_in, const int* in_sizes, int n_in,
                              void* d_out, int out_size) {
    const int*   shape_type = (const int*)d_in[0];
    const float* params     = (const float*)d_in[1];
    const float* textures   = (const float*)d_in[2];
    float* out = (float*)d_out;

    dim3 bgrid(QDIM, 4);
    build_quad_kernel<<<bgrid, 256>>>(textures);

    dim3 blk(32, 8);
    dim3 grd(CANVAS / 32, CANVAS / 8);
    render_kernel<<<grd, blk>>>(shape_type, params, out);
}

// round 5
// speedup vs baseline: 1.4236x; 1.4236x over previous
#include <cuda_runtime.h>
#include <cuda_fp16.h>

#define CANVAS 1024
#define NSH 64
#define TEXN 512
#define QDIM 513                 // tap-origin range (+1 offset): 0..512
#define QPAIR 257                // ceil(QDIM/2), 2x2 morton blocks per axis
#define QT (QPAIR * QPAIR * 4)   // entries per texture (swizzled, padded)
#define T_EPS 1e-5f

// One quad entry = the 2x2 bilinear tap block for tap-origin (yi, xi):
//   a: v00.rg, v00.ba, v01.rg, v01.ba   (fp16 pairs)
//   b: v10.rg, v10.ba, v11.rg, v11.ba
// Out-of-bounds taps stored as zero (matches reference zero-fill).
// Layout: 2x2 Morton blocks -> one 128B line = 2x2 neighborhood of tap origins.
struct __align__(32) Quad { uint4 a, b; };

__device__ Quad g_quad[4 * QT];   // ~33.8 MB scratch

__device__ __forceinline__ int quad_off(int qy, int qx) {
    return ((((qy >> 1) * QPAIR + (qx >> 1)) << 2) | ((qy & 1) << 1) | (qx & 1));
}

// Per-shape transform/color record (compacted into smem per tile).
struct __align__(16) ShapeXfm {
    float tx, ty, m00, m01;
    float m10, m11, r, g;
    float b; int texoff; float pad0, pad1;
};

// ---------------------------------------------------------------------------
// Kernel 1: build fp16 quad-gather table (Morton-swizzled).
// grid: (QDIM rows, 4 tex), block 256.
// ---------------------------------------------------------------------------
__global__ __launch_bounds__(256) void build_quad_kernel(const float* __restrict__ tex) {
    int t  = blockIdx.y;
    int qy = blockIdx.x;                   // 0..512
    int yi = qy - 1;                       // -1..511
    const int NPIX = TEXN * TEXN;
    const float* base = tex + (size_t)t * 4 * NPIX;
    Quad* qbase = g_quad + t * QT;

    for (int qx = threadIdx.x; qx < QDIM; qx += 256) {
        int xi = qx - 1;                   // -1..511

        float vals[4][4];  // [tap][chan]
        #pragma unroll
        for (int ty2 = 0; ty2 < 2; ty2++) {
            #pragma unroll
            for (int tx2 = 0; tx2 < 2; tx2++) {
                int y = yi + ty2, x = xi + tx2;
                bool ok = ((unsigned)x < (unsigned)TEXN) && ((unsigned)y < (unsigned)TEXN);
                int off = y * TEXN + x;
                #pragma unroll
                for (int ch = 0; ch < 4; ch++)
                    vals[ty2 * 2 + tx2][ch] = ok ? __ldg(base + ch * NPIX + off) : 0.0f;
            }
        }

        __half2 h[8];
        #pragma unroll
        for (int tap = 0; tap < 4; tap++) {
            h[tap * 2 + 0] = __floats2half2_rn(vals[tap][0], vals[tap][1]);
            h[tap * 2 + 1] = __floats2half2_rn(vals[tap][2], vals[tap][3]);
        }

        Quad q;
        q.a = *reinterpret_cast<uint4*>(&h[0]);
        q.b = *reinterpret_cast<uint4*>(&h[4]);
        qbase[quad_off(qy, qx)] = q;
    }
}

// ---------------------------------------------------------------------------
// Kernel 2: render. One thread per pixel. Per-tile shape compaction,
// reverse-order compositing with transmittance early-exit, fp16 bilerp.
// ---------------------------------------------------------------------------
__global__ __launch_bounds__(256) void render_kernel(const int* __restrict__ st,
                                                     const float* __restrict__ params,
                                                     float* __restrict__ out) {
    __shared__ ShapeXfm sxf[NSH];     // compacted, order-preserving
    __shared__ int s_cnt0;            // warp0 pass count
    __shared__ int s_nlive;

    int tid = threadIdx.y * 32 + threadIdx.x;

    // tile bounds (pixel centers)
    float tX0 = (float)(blockIdx.x * 32) + 0.5f;
    float tX1 = tX0 + 31.0f;
    float tY0 = (float)(blockIdx.y * 8) + 0.5f;
    float tY1 = tY0 + 7.0f;

    // --- per-tile shape prep + compaction (first 2 warps) ---
    bool pass = false;
    ShapeXfm xf;
    if (tid < NSH) {
        const float* p = params + tid * 9;
        float tx = p[0] * (float)CANVAS;
        float ty = p[1] * (float)CANVAS;
        float W  = (float)CANVAS * (0.05f + 0.95f * p[2]);
        float H  = (float)CANVAS * (0.05f + 0.95f * p[3]);
        float as = p[4], ac = p[5];
        float nrm = sqrtf(as * as + ac * ac) + 1e-8f;
        float c = ac / nrm, s = as / nrm;
        float fx = (float)TEXN / W;
        float fy = (float)TEXN / H;

        xf.tx = tx; xf.ty = ty;
        xf.m00 =  c * fx;  xf.m01 = s * fx;
        xf.m10 = -s * fy;  xf.m11 = c * fy;
        xf.r = p[6]; xf.g = p[7]; xf.b = p[8];
        xf.texoff = st[tid] * QT;
        xf.pad0 = xf.pad1 = 0.f;

        float uh = 0.5f * W * (1.0f + 2.0f / TEXN) + 2.0f;
        float vh = 0.5f * H * (1.0f + 2.0f / TEXN) + 2.0f;
        float ex = fabsf(c) * uh + fabsf(s) * vh;
        float ey = fabsf(s) * uh + fabsf(c) * vh;
        pass = !(tX1 < tx - ex || tX0 > tx + ex || tY1 < ty - ey || tY0 > ty + ey);
    }

    unsigned mask = 0;
    int pos = 0;
    if (tid < NSH) {
        mask = __ballot_sync(0xffffffffu, pass);
        pos = __popc(mask & ((1u << (tid & 31)) - 1u));
        if ((tid & 31) == 0) {
            if (tid == 0) s_cnt0 = __popc(mask);
            else          s_nlive = __popc(mask);   // warp1 count (partial)
        }
    }
    __syncthreads();
    if (tid < NSH) {
        int base = (tid < 32) ? 0 : s_cnt0;
        if (pass) sxf[base + pos] = xf;
        if (tid == 32) s_nlive = s_cnt0 + __popc(mask);
        if (tid == 0 && NSH <= 32) s_nlive = s_cnt0;
    }
    __syncthreads();

    int nlive = s_nlive;

    int x = blockIdx.x * 32 + threadIdx.x;
    int y = blockIdx.y * 8 + threadIdx.y;
    float px = (float)x + 0.5f;
    float py = (float)y + 0.5f;

    // Reverse compositing: out = C + T * canvas0(=1)
    float Cr = 0.0f, Cg = 0.0f, Cb = 0.0f;
    float T = 1.0f;

    for (int k = nlive - 1; k >= 0; k--) {
        if (__all_sync(0xffffffffu, T <= T_EPS)) break;
        if (T <= T_EPS) continue;

        const ShapeXfm rec = sxf[k];
        float dx = px - rec.tx;
        float dy = py - rec.ty;
        // fu = u + 1, fv = v + 1  (255.5 + 1 folded into constant)
        float fu = fmaf(rec.m00, dx, fmaf(rec.m01, dy, 256.5f));
        float fv = fmaf(rec.m10, dx, fmaf(rec.m11, dy, 256.5f));
        int xi1 = __float2int_rd(fu);   // floor; valid tap-origin index 0..512
        int yi1 = __float2int_rd(fv);
        if (((unsigned)xi1 >= (unsigned)QDIM) || ((unsigned)yi1 >= (unsigned)QDIM))
            continue;

        float wx = fu - (float)xi1;
        float wy = fv - (float)yi1;

        const uint4* q = reinterpret_cast<const uint4*>(
            g_quad + rec.texoff + quad_off(yi1, xi1));
        uint4 qa = __ldg(q);
        uint4 qb = __ldg(q + 1);

        __half2 rg00 = *reinterpret_cast<const __half2*>(&qa.x);
        __half2 ba00 = *reinterpret_cast<const __half2*>(&qa.y);
        __half2 rg01 = *reinterpret_cast<const __half2*>(&qa.z);
        __half2 ba01 = *reinterpret_cast<const __half2*>(&qa.w);
        __half2 rg10 = *reinterpret_cast<const __half2*>(&qb.x);
        __half2 ba10 = *reinterpret_cast<const __half2*>(&qb.y);
        __half2 rg11 = *reinterpret_cast<const __half2*>(&qb.z);
        __half2 ba11 = *reinterpret_cast<const __half2*>(&qb.w);

        __half2 wx2 = __float2half2_rn(wx);
        __half2 wy2 = __float2half2_rn(wy);

        __half2 rg_t = __hfma2(wx2, __hsub2(rg01, rg00), rg00);
        __half2 ba_t = __hfma2(wx2, __hsub2(ba01, ba00), ba00);
        __half2 rg_b = __hfma2(wx2, __hsub2(rg11, rg10), rg10);
        __half2 ba_b = __hfma2(wx2, __hsub2(ba11, ba10), ba10);
        __half2 rg   = __hfma2(wy2, __hsub2(rg_b, rg_t), rg_t);
        __half2 ba   = __hfma2(wy2, __hsub2(ba_b, ba_t), ba_t);

        float2 rgf = __half22float2(rg);
        float2 baf = __half22float2(ba);
        float sr = rgf.x, sg = rgf.y, sb = baf.x, sa = baf.y;

        float Ta = T * sa;
        Cr = fmaf(Ta, sr * rec.r, Cr);
        Cg = fmaf(Ta, sg * rec.g, Cg);
        Cb = fmaf(Ta, sb * rec.b, Cb);
        T  = T - Ta;            // T *= (1 - sa)
    }

    int o = y * CANVAS + x;
    out[o] = Cr + T;
    out[CANVAS * CANVAS + o] = Cg + T;
    out[2 * CANVAS * CANVAS + o] = Cb + T;
}

// ---------------------------------------------------------------------------
extern "C" void kernel_launch(void* const* d_in, const int* in_sizes, int n_in,
                              void* d_out, int out_size) {
    const int*   shape_type = (const int*)d_in[0];
    const float* params     = (const float*)d_in[1];
    const float* textures   = (const float*)d_in[2];
    float* out = (float*)d_out;

    dim3 bgrid(QDIM, 4);
    build_quad_kernel<<<bgrid, 256>>>(textures);

    dim3 blk(32, 8);
    dim3 grd(CANVAS / 32, CANVAS / 8);
    render_kernel<<<grd, blk>>>(shape_type, params, out);
}